// round 1
// baseline (speedup 1.0000x reference)
#include <cuda_runtime.h>

#define N_NODES 100000
#define N_EDGES 1600000
#define D 128
#define L_LAYERS 3

// ---------------- scratch (no allocations allowed) ----------------
__device__ int   g_deg[N_NODES];
__device__ float g_invdeg[N_NODES];
__device__ int   g_off[N_NODES + 1];
__device__ int   g_cursor[N_NODES];
__device__ int   g_csr[N_EDGES];
__device__ float g_h0[(size_t)N_NODES * D];
__device__ float g_h1[(size_t)N_NODES * D];
__device__ float g_hn[(size_t)N_NODES * D];

// ---------------- CSR build ----------------
__global__ void zero_deg_kernel() {
    int i = blockIdx.x * blockDim.x + threadIdx.x;
    if (i < N_NODES) g_deg[i] = 0;
}

__global__ void count_deg_kernel(const int* __restrict__ dst) {
    int e = blockIdx.x * blockDim.x + threadIdx.x;
    if (e < N_EDGES) atomicAdd(&g_deg[dst[e]], 1);
}

// Single-block exclusive scan of g_deg -> g_off; also writes inv_deg and
// zeroes cursors.
__global__ void scan_offsets_kernel() {
    __shared__ int warp_sums[32];
    __shared__ int carry_sh;
    int t = threadIdx.x, lane = t & 31, w = t >> 5;
    if (t == 0) carry_sh = 0;
    __syncthreads();
    for (int base = 0; base < N_NODES; base += 1024) {
        int i = base + t;
        int v = (i < N_NODES) ? g_deg[i] : 0;
        int incl = v;
        #pragma unroll
        for (int off = 1; off < 32; off <<= 1) {
            int x = __shfl_up_sync(0xffffffffu, incl, off);
            if (lane >= off) incl += x;
        }
        if (lane == 31) warp_sums[w] = incl;
        __syncthreads();
        if (w == 0) {
            int s = warp_sums[lane];
            #pragma unroll
            for (int off = 1; off < 32; off <<= 1) {
                int x = __shfl_up_sync(0xffffffffu, s, off);
                if (lane >= off) s += x;
            }
            warp_sums[lane] = s;  // inclusive scan of warp sums
        }
        __syncthreads();
        int carry = carry_sh;
        int woff = (w > 0) ? warp_sums[w - 1] : 0;
        if (i < N_NODES) {
            g_off[i] = carry + woff + incl - v;  // exclusive prefix
            g_invdeg[i] = 1.0f / (float)max(v, 1);
            g_cursor[i] = 0;
        }
        __syncthreads();
        if (t == 1023) carry_sh = carry + woff + incl;  // += block total
        __syncthreads();
    }
    if (t == 0) g_off[N_NODES] = carry_sh;
}

__global__ void fill_csr_kernel(const int* __restrict__ src,
                                const int* __restrict__ dst) {
    int e = blockIdx.x * blockDim.x + threadIdx.x;
    if (e < N_EDGES) {
        int d = dst[e];
        int p = atomicAdd(&g_cursor[d], 1);
        g_csr[g_off[d] + p] = src[e];
    }
}

// ---------------- aggregation: one warp per node, pull via CSR ----------------
__global__ void aggregate_kernel(const float* __restrict__ hin) {
    int gw = (blockIdx.x * blockDim.x + threadIdx.x) >> 5;
    int lane = threadIdx.x & 31;
    if (gw >= N_NODES) return;
    int s = g_off[gw], e = g_off[gw + 1];
    const float4* H = (const float4*)hin;
    float4 acc = make_float4(0.f, 0.f, 0.f, 0.f);
    for (int j = s; j < e; j++) {
        int u = __ldg(&g_csr[j]);
        float4 v = __ldg(&H[(size_t)u * 32 + lane]);
        acc.x += v.x; acc.y += v.y; acc.z += v.z; acc.w += v.w;
    }
    float inv = g_invdeg[gw];
    float4 r = make_float4(acc.x * inv, acc.y * inv, acc.z * inv, acc.w * inv);
    ((float4*)g_hn)[(size_t)gw * 32 + lane] = r;
}

// ---------------- fused GEMM: out = relu(hin@Ws + hn@Wn + bias) --------------
#define SMEM_FLOATS (256 * 128 + 64 * 32)
#define SMEM_BYTES (SMEM_FLOATS * 4)

__global__ void __launch_bounds__(256, 1) sage_gemm_kernel(
    const float* __restrict__ hin, const float* __restrict__ hn,
    const float* __restrict__ Ws, const float* __restrict__ Wn,
    const float* __restrict__ bias, float* __restrict__ out)
{
    extern __shared__ float smem[];
    float* sW = smem;              // [256][128]: rows 0-127 = Ws, 128-255 = Wn
    float* sA = smem + 256 * 128;  // [64][32]
    int tid = threadIdx.x;

    float4* sW4 = (float4*)sW;
    const float4* Ws4 = (const float4*)Ws;
    const float4* Wn4 = (const float4*)Wn;
    #pragma unroll
    for (int i = 0; i < 16; i++) {
        int idx = tid + 256 * i;          // 4096 float4 per weight matrix
        sW4[idx] = __ldg(&Ws4[idx]);
        sW4[idx + 4096] = __ldg(&Wn4[idx]);
    }

    int m0 = blockIdx.x * 64;
    int tx = tid & 15, ty = tid >> 4;     // thread -> 4 rows x 8 cols microtile
    float acc[4][8];
    #pragma unroll
    for (int i = 0; i < 4; i++)
        #pragma unroll
        for (int j = 0; j < 8; j++) acc[i][j] = 0.f;

    for (int kt = 0; kt < 8; kt++) {
        const float* srcp = (kt < 4) ? hin : hn;
        int kc0 = (kt & 3) * 32;
        __syncthreads();  // also covers sW loads on first iteration
        #pragma unroll
        for (int i = 0; i < 2; i++) {
            int Lx = tid + 256 * i;       // 512 float4 total
            int r = Lx >> 3, c4 = Lx & 7;
            int m = m0 + r;
            float4 val = make_float4(0.f, 0.f, 0.f, 0.f);
            if (m < N_NODES)
                val = __ldg((const float4*)(srcp + (size_t)m * D + kc0 + c4 * 4));
            ((float4*)sA)[r * 8 + c4] = val;
        }
        __syncthreads();
        #pragma unroll 8
        for (int k = 0; k < 32; k++) {
            const float* wrow = &sW[(kt * 32 + k) * D + tx * 8];
            float4 b0 = *(const float4*)(wrow);
            float4 b1 = *(const float4*)(wrow + 4);
            float bb[8] = {b0.x, b0.y, b0.z, b0.w, b1.x, b1.y, b1.z, b1.w};
            float aa[4];
            #pragma unroll
            for (int i = 0; i < 4; i++) aa[i] = sA[(ty * 4 + i) * 32 + k];
            #pragma unroll
            for (int i = 0; i < 4; i++)
                #pragma unroll
                for (int j = 0; j < 8; j++)
                    acc[i][j] += aa[i] * bb[j];
        }
    }

    float bset[8];
    #pragma unroll
    for (int j = 0; j < 8; j++) bset[j] = __ldg(&bias[tx * 8 + j]);
    #pragma unroll
    for (int i = 0; i < 4; i++) {
        int m = m0 + ty * 4 + i;
        if (m < N_NODES) {
            float r[8];
            #pragma unroll
            for (int j = 0; j < 8; j++) {
                float v = acc[i][j] + bset[j];
                r[j] = v > 0.f ? v : 0.f;
            }
            float4* op = (float4*)(out + (size_t)m * D + tx * 8);
            op[0] = make_float4(r[0], r[1], r[2], r[3]);
            op[1] = make_float4(r[4], r[5], r[6], r[7]);
        }
    }
}

// ---------------- launch ----------------
extern "C" void kernel_launch(void* const* d_in, const int* in_sizes, int n_in,
                              void* d_out, int out_size)
{
    const float* x       = (const float*)d_in[0];
    const float* W_self  = (const float*)d_in[1];
    const float* W_neigh = (const float*)d_in[2];
    const float* bias    = (const float*)d_in[3];
    const int*   src     = (const int*)d_in[4];
    const int*   dst     = (const int*)d_in[5];
    float* out = (float*)d_out;

    void *p0, *p1, *pn;
    cudaGetSymbolAddress(&p0, g_h0);
    cudaGetSymbolAddress(&p1, g_h1);
    cudaGetSymbolAddress(&pn, g_hn);
    float* h0 = (float*)p0;
    float* h1 = (float*)p1;
    float* hn = (float*)pn;

    cudaFuncSetAttribute(sage_gemm_kernel,
                         cudaFuncAttributeMaxDynamicSharedMemorySize, SMEM_BYTES);

    zero_deg_kernel<<<(N_NODES + 255) / 256, 256>>>();
    count_deg_kernel<<<(N_EDGES + 255) / 256, 256>>>(dst);
    scan_offsets_kernel<<<1, 1024>>>();
    fill_csr_kernel<<<(N_EDGES + 255) / 256, 256>>>(src, dst);

    const float* hin = x;
    float* houts[3] = {h0, h1, out};
    for (int l = 0; l < L_LAYERS; l++) {
        aggregate_kernel<<<(N_NODES + 7) / 8, 256>>>(hin);
        sage_gemm_kernel<<<(N_NODES + 63) / 64, 256, SMEM_BYTES>>>(
            hin, hn,
            W_self + (size_t)l * D * D, W_neigh + (size_t)l * D * D,
            bias + (size_t)l * D, houts[l]);
        hin = houts[l];
    }
}

// round 2
// speedup vs baseline: 1.6744x; 1.6744x over previous
#include <cuda_runtime.h>
#include <cuda_bf16.h>
#include <cstdint>

#define N_NODES 100000
#define N_EDGES 1600000
#define D 128
#define L_LAYERS 3

#define KPAD 272   // bf16 units per weight row (256 data + pad, bank-friendly)
#define APAD 48    // bf16 units per A-tile row (32 data + pad, bank-friendly)

// ---------------- scratch (no allocations allowed) ----------------
__device__ int   g_deg[N_NODES];
__device__ float g_invdeg[N_NODES];
__device__ int   g_off[N_NODES + 1];
__device__ int   g_cursor[N_NODES];
__device__ int   g_csr[N_EDGES];
__device__ float g_h0[(size_t)N_NODES * D];
__device__ float g_h1[(size_t)N_NODES * D];
__device__ float g_hn[(size_t)N_NODES * D];
// transposed + bf16-split weights, permuted-K layout: [n=128][KPAD]
__device__ __align__(16) __nv_bfloat16 g_wthi[128 * KPAD];
__device__ __align__(16) __nv_bfloat16 g_wtlo[128 * KPAD];

// ---------------- CSR build ----------------
__global__ void zero_deg_kernel() {
    int i = blockIdx.x * blockDim.x + threadIdx.x;
    if (i < N_NODES) g_deg[i] = 0;
}

__global__ void count_deg_kernel(const int* __restrict__ dst) {
    int e = blockIdx.x * blockDim.x + threadIdx.x;
    if (e < N_EDGES) atomicAdd(&g_deg[dst[e]], 1);
}

__global__ void scan_offsets_kernel() {
    __shared__ int warp_sums[32];
    __shared__ int carry_sh;
    int t = threadIdx.x, lane = t & 31, w = t >> 5;
    if (t == 0) carry_sh = 0;
    __syncthreads();
    for (int base = 0; base < N_NODES; base += 1024) {
        int i = base + t;
        int v = (i < N_NODES) ? g_deg[i] : 0;
        int incl = v;
        #pragma unroll
        for (int off = 1; off < 32; off <<= 1) {
            int x = __shfl_up_sync(0xffffffffu, incl, off);
            if (lane >= off) incl += x;
        }
        if (lane == 31) warp_sums[w] = incl;
        __syncthreads();
        if (w == 0) {
            int s = warp_sums[lane];
            #pragma unroll
            for (int off = 1; off < 32; off <<= 1) {
                int x = __shfl_up_sync(0xffffffffu, s, off);
                if (lane >= off) s += x;
            }
            warp_sums[lane] = s;
        }
        __syncthreads();
        int carry = carry_sh;
        int woff = (w > 0) ? warp_sums[w - 1] : 0;
        if (i < N_NODES) {
            g_off[i] = carry + woff + incl - v;
            g_invdeg[i] = 1.0f / (float)max(v, 1);
            g_cursor[i] = 0;
        }
        __syncthreads();
        if (t == 1023) carry_sh = carry + woff + incl;
        __syncthreads();
    }
    if (t == 0) g_off[N_NODES] = carry_sh;
}

__global__ void fill_csr_kernel(const int* __restrict__ src,
                                const int* __restrict__ dst) {
    int e = blockIdx.x * blockDim.x + threadIdx.x;
    if (e < N_EDGES) {
        int d = dst[e];
        int p = atomicAdd(&g_cursor[d], 1);
        g_csr[g_off[d] + p] = src[e];
    }
}

// ---------------- aggregation: one warp per node, pull via CSR ----------------
__global__ void aggregate_kernel(const float* __restrict__ hin) {
    int gw = (blockIdx.x * blockDim.x + threadIdx.x) >> 5;
    int lane = threadIdx.x & 31;
    if (gw >= N_NODES) return;
    int s = g_off[gw], e = g_off[gw + 1];
    const float4* H = (const float4*)hin;
    float4 acc = make_float4(0.f, 0.f, 0.f, 0.f);
    for (int j = s; j < e; j++) {
        int u = __ldg(&g_csr[j]);
        float4 v = __ldg(&H[(size_t)u * 32 + lane]);
        acc.x += v.x; acc.y += v.y; acc.z += v.z; acc.w += v.w;
    }
    float inv = g_invdeg[gw];
    float4 r = make_float4(acc.x * inv, acc.y * inv, acc.z * inv, acc.w * inv);
    ((float4*)g_hn)[(size_t)gw * 32 + lane] = r;
}

// ---------------- weight prep: transpose + bf16 hi/lo split + K-permute ------
// Combined weight [256,128] = [Ws ; Wn]; stored as [n][k_phys] with per-16
// K-group permutation [0,1,8,9,2,3,10,11,4,5,12,13,6,7,14,15] so an mma
// fragment pair {b0,b1} = one 8-byte LDS.
__global__ void prep_w_kernel(const float* __restrict__ Ws,
                              const float* __restrict__ Wn) {
    int idx = blockIdx.x * blockDim.x + threadIdx.x;
    if (idx >= 128 * 256) return;
    int n = idx >> 8;
    int k = idx & 255;
    float w = (k < 128) ? Ws[k * 128 + n] : Wn[(k - 128) * 128 + n];
    __nv_bfloat16 hi = __float2bfloat16(w);
    __nv_bfloat16 lo = __float2bfloat16(w - __bfloat162float(hi));
    int group = k >> 4, l = k & 15;
    int p = ((l & 7) >> 1) * 4 + (l & 1) + ((l >> 3) << 1);
    int off = n * KPAD + group * 16 + p;
    g_wthi[off] = hi;
    g_wtlo[off] = lo;
}

// ---------------- bf16-split tensor-core GEMM ------------------------------
// out = relu([hin|hn] @ [Ws;Wn] + bias) using
//   C = Ahi*Whi + Alo*Whi + Ahi*Wlo  (fp32 accum, m16n8k16 bf16 mma.sync)
#define GEMM_SMEM_BYTES ((2 * 128 * KPAD + 2 * 128 * APAD) * 2)  // 163840

__device__ __forceinline__ void mma_bf16(float c[4], uint32_t a0, uint32_t a1,
                                         uint32_t a2, uint32_t a3,
                                         uint32_t b0, uint32_t b1) {
    asm volatile(
        "mma.sync.aligned.m16n8k16.row.col.f32.bf16.bf16.f32 "
        "{%0,%1,%2,%3}, {%4,%5,%6,%7}, {%8,%9}, {%0,%1,%2,%3};"
        : "+f"(c[0]), "+f"(c[1]), "+f"(c[2]), "+f"(c[3])
        : "r"(a0), "r"(a1), "r"(a2), "r"(a3), "r"(b0), "r"(b1));
}

__global__ void __launch_bounds__(256, 1) sage_gemm_bf16_kernel(
    const float* __restrict__ hin, const float* __restrict__ hn,
    const float* __restrict__ bias, float* __restrict__ out)
{
    extern __shared__ __align__(16) __nv_bfloat16 smem[];
    __nv_bfloat16* sWhi = smem;                      // [128][KPAD]
    __nv_bfloat16* sWlo = sWhi + 128 * KPAD;         // [128][KPAD]
    __nv_bfloat16* sAhi = sWlo + 128 * KPAD;         // [128][APAD]
    __nv_bfloat16* sAlo = sAhi + 128 * APAD;         // [128][APAD]

    int tid = threadIdx.x;
    int lane = tid & 31, warp = tid >> 5;
    int warpM = warp & 3, warpN = warp >> 2;         // 4 x 2 warp grid
    int g = lane >> 2, tig = lane & 3;
    int m0 = blockIdx.x * 128;

    // stage weights (already split/permuted) into smem: 4352 uint4 per array
    {
        const uint4* s0 = (const uint4*)g_wthi;
        const uint4* s1 = (const uint4*)g_wtlo;
        uint4* d0 = (uint4*)sWhi;
        uint4* d1 = (uint4*)sWlo;
        for (int i = tid; i < (128 * KPAD) / 8; i += 256) {
            d0[i] = s0[i];
            d1[i] = s1[i];
        }
    }

    float acc[2][8][4];
    #pragma unroll
    for (int mf = 0; mf < 2; mf++)
        #pragma unroll
        for (int nf = 0; nf < 8; nf++)
            #pragma unroll
            for (int r = 0; r < 4; r++) acc[mf][nf][r] = 0.f;

    // physical pair offsets within a 16-K group, indexed by (c4 & 3)
    const int ptab[4] = {0, 8, 2, 10};

    for (int kc = 0; kc < 8; kc++) {
        const float* srcp = (kc < 4) ? hin : hn;
        int koff = (kc & 3) * 32;
        __syncthreads();   // previous chunk's mma reads done; also covers W stage
        // load 128x32 fp32, convert to hi/lo bf16, permuted-K smem
        #pragma unroll
        for (int i = 0; i < 4; i++) {
            int idx = tid + 256 * i;       // 1024 float4
            int r = idx >> 3, c4 = idx & 7;
            int m = m0 + r;
            float4 v = make_float4(0.f, 0.f, 0.f, 0.f);
            if (m < N_NODES)
                v = __ldg((const float4*)(srcp + (size_t)m * D + koff + c4 * 4));
            __nv_bfloat16 hx = __float2bfloat16(v.x);
            __nv_bfloat16 hy = __float2bfloat16(v.y);
            __nv_bfloat16 hz = __float2bfloat16(v.z);
            __nv_bfloat16 hw = __float2bfloat16(v.w);
            __nv_bfloat16 lx = __float2bfloat16(v.x - __bfloat162float(hx));
            __nv_bfloat16 ly = __float2bfloat16(v.y - __bfloat162float(hy));
            __nv_bfloat16 lz = __float2bfloat16(v.z - __bfloat162float(hz));
            __nv_bfloat16 lw = __float2bfloat16(v.w - __bfloat162float(hw));
            uint32_t hp0 = ((uint32_t)__bfloat16_as_ushort(hy) << 16) |
                           __bfloat16_as_ushort(hx);
            uint32_t hp1 = ((uint32_t)__bfloat16_as_ushort(hw) << 16) |
                           __bfloat16_as_ushort(hz);
            uint32_t lp0 = ((uint32_t)__bfloat16_as_ushort(ly) << 16) |
                           __bfloat16_as_ushort(lx);
            uint32_t lp1 = ((uint32_t)__bfloat16_as_ushort(lw) << 16) |
                           __bfloat16_as_ushort(lz);
            int group = c4 >> 2;
            int p0 = ptab[c4 & 3];
            int base = r * APAD + group * 16;      // bf16 units, even
            uint32_t* AH = (uint32_t*)sAhi;
            uint32_t* AL = (uint32_t*)sAlo;
            AH[(base + p0) >> 1]     = hp0;
            AH[(base + p0 + 4) >> 1] = hp1;
            AL[(base + p0) >> 1]     = lp0;
            AL[(base + p0 + 4) >> 1] = lp1;
        }
        __syncthreads();
        #pragma unroll
        for (int ks = 0; ks < 2; ks++) {
            int ka = ks * 16;                 // within A chunk (physical)
            int kw = kc * 32 + ks * 16;       // within W row (physical)
            uint32_t Ah[2][4], Al[2][4];
            #pragma unroll
            for (int mf = 0; mf < 2; mf++) {
                int r0 = warpM * 32 + mf * 16;
                uint2 t0 = *(const uint2*)&sAhi[(r0 + g) * APAD + ka + tig * 4];
                uint2 t1 = *(const uint2*)&sAhi[(r0 + g + 8) * APAD + ka + tig * 4];
                Ah[mf][0] = t0.x; Ah[mf][1] = t1.x; Ah[mf][2] = t0.y; Ah[mf][3] = t1.y;
                uint2 u0 = *(const uint2*)&sAlo[(r0 + g) * APAD + ka + tig * 4];
                uint2 u1 = *(const uint2*)&sAlo[(r0 + g + 8) * APAD + ka + tig * 4];
                Al[mf][0] = u0.x; Al[mf][1] = u1.x; Al[mf][2] = u0.y; Al[mf][3] = u1.y;
            }
            #pragma unroll
            for (int nf = 0; nf < 8; nf++) {
                int nr = warpN * 64 + nf * 8 + g;
                uint2 bh = *(const uint2*)&sWhi[nr * KPAD + kw + tig * 4];
                uint2 bl = *(const uint2*)&sWlo[nr * KPAD + kw + tig * 4];
                #pragma unroll
                for (int mf = 0; mf < 2; mf++) {
                    mma_bf16(acc[mf][nf], Ah[mf][0], Ah[mf][1], Ah[mf][2], Ah[mf][3], bh.x, bh.y);
                    mma_bf16(acc[mf][nf], Al[mf][0], Al[mf][1], Al[mf][2], Al[mf][3], bh.x, bh.y);
                    mma_bf16(acc[mf][nf], Ah[mf][0], Ah[mf][1], Ah[mf][2], Ah[mf][3], bl.x, bl.y);
                }
            }
        }
    }

    // epilogue: + bias, relu, store
    #pragma unroll
    for (int mf = 0; mf < 2; mf++) {
        #pragma unroll
        for (int nf = 0; nf < 8; nf++) {
            int row0 = m0 + warpM * 32 + mf * 16 + g;
            int col = warpN * 64 + nf * 8 + tig * 2;
            float bx = __ldg(&bias[col]);
            float by = __ldg(&bias[col + 1]);
            if (row0 < N_NODES) {
                float r0 = acc[mf][nf][0] + bx; r0 = r0 > 0.f ? r0 : 0.f;
                float r1 = acc[mf][nf][1] + by; r1 = r1 > 0.f ? r1 : 0.f;
                *(float2*)&out[(size_t)row0 * D + col] = make_float2(r0, r1);
            }
            if (row0 + 8 < N_NODES) {
                float r2 = acc[mf][nf][2] + bx; r2 = r2 > 0.f ? r2 : 0.f;
                float r3 = acc[mf][nf][3] + by; r3 = r3 > 0.f ? r3 : 0.f;
                *(float2*)&out[(size_t)(row0 + 8) * D + col] = make_float2(r2, r3);
            }
        }
    }
}

// ---------------- launch ----------------
extern "C" void kernel_launch(void* const* d_in, const int* in_sizes, int n_in,
                              void* d_out, int out_size)
{
    const float* x       = (const float*)d_in[0];
    const float* W_self  = (const float*)d_in[1];
    const float* W_neigh = (const float*)d_in[2];
    const float* bias    = (const float*)d_in[3];
    const int*   src     = (const int*)d_in[4];
    const int*   dst     = (const int*)d_in[5];
    float* out = (float*)d_out;

    void *p0, *p1, *pn;
    cudaGetSymbolAddress(&p0, g_h0);
    cudaGetSymbolAddress(&p1, g_h1);
    cudaGetSymbolAddress(&pn, g_hn);
    float* h0 = (float*)p0;
    float* h1 = (float*)p1;
    float* hn = (float*)pn;

    cudaFuncSetAttribute(sage_gemm_bf16_kernel,
                         cudaFuncAttributeMaxDynamicSharedMemorySize,
                         GEMM_SMEM_BYTES);

    zero_deg_kernel<<<(N_NODES + 255) / 256, 256>>>();
    count_deg_kernel<<<(N_EDGES + 255) / 256, 256>>>(dst);
    scan_offsets_kernel<<<1, 1024>>>();
    fill_csr_kernel<<<(N_EDGES + 255) / 256, 256>>>(src, dst);

    const float* hin = x;
    float* houts[3] = {h0, h1, out};
    int gemm_grid = (N_NODES + 127) / 128;   // 782
    for (int l = 0; l < L_LAYERS; l++) {
        prep_w_kernel<<<128, 256>>>(W_self + (size_t)l * D * D,
                                    W_neigh + (size_t)l * D * D);
        aggregate_kernel<<<(N_NODES + 7) / 8, 256>>>(hin);
        sage_gemm_bf16_kernel<<<gemm_grid, 256, GEMM_SMEM_BYTES>>>(
            hin, hn, bias + (size_t)l * D, houts[l]);
        hin = houts[l];
    }
}

// round 3
// speedup vs baseline: 2.1410x; 1.2786x over previous
#include <cuda_runtime.h>
#include <cuda_bf16.h>
#include <cstdint>

#define N_NODES 100000
#define N_EDGES 1600000
#define D 128
#define L_LAYERS 3

#define KPAD 272   // bf16 units per weight row (256 data + pad)
#define APAD 48    // bf16 units per A-tile row (32 data + pad)
#define GEMM_TILES ((N_NODES + 127) / 128)   // 782
#define GEMM_GRID 148

// ---------------- scratch (no allocations allowed) ----------------
__device__ int   g_deg[N_NODES];
__device__ float g_invdeg[N_NODES];
__device__ int   g_off[N_NODES + 1];
__device__ int   g_cursor[N_NODES];
__device__ int   g_csr[N_EDGES];
__device__ float g_h0[(size_t)N_NODES * D];
__device__ float g_h1[(size_t)N_NODES * D];
__device__ float g_hn[(size_t)N_NODES * D];
// transposed + bf16-split weights, permuted-K layout: [n=128][KPAD]
__device__ __align__(16) __nv_bfloat16 g_wthi[128 * KPAD];
__device__ __align__(16) __nv_bfloat16 g_wtlo[128 * KPAD];

// ---------------- CSR build ----------------
__global__ void zero_deg_kernel() {
    int i = blockIdx.x * blockDim.x + threadIdx.x;
    if (i < N_NODES) g_deg[i] = 0;
}

__global__ void count_deg_kernel(const int* __restrict__ dst) {
    int e = blockIdx.x * blockDim.x + threadIdx.x;
    if (e < N_EDGES) atomicAdd(&g_deg[dst[e]], 1);
}

// Single-block scan, 4 elements/thread/iter (25 iterations).
__global__ void scan_offsets_kernel() {
    __shared__ int warp_sums[32];
    __shared__ int carry_sh;
    int t = threadIdx.x, lane = t & 31, w = t >> 5;
    if (t == 0) carry_sh = 0;
    __syncthreads();
    for (int base = 0; base < N_NODES; base += 4096) {
        int i4 = base + t * 4;
        int4 v = make_int4(0, 0, 0, 0);
        if (i4 < N_NODES) v = *(const int4*)&g_deg[i4];
        int s0 = v.x, s1 = s0 + v.y, s2 = s1 + v.z, s3 = s2 + v.w;
        int incl = s3;
        #pragma unroll
        for (int off = 1; off < 32; off <<= 1) {
            int x = __shfl_up_sync(0xffffffffu, incl, off);
            if (lane >= off) incl += x;
        }
        if (lane == 31) warp_sums[w] = incl;
        __syncthreads();
        if (w == 0) {
            int s = warp_sums[lane];
            #pragma unroll
            for (int off = 1; off < 32; off <<= 1) {
                int x = __shfl_up_sync(0xffffffffu, s, off);
                if (lane >= off) s += x;
            }
            warp_sums[lane] = s;
        }
        __syncthreads();
        int carry = carry_sh;
        int woff = (w > 0) ? warp_sums[w - 1] : 0;
        int excl = carry + woff + incl - s3;
        if (i4 < N_NODES) {
            *(int4*)&g_off[i4] =
                make_int4(excl, excl + s0, excl + s1, excl + s2);
            *(float4*)&g_invdeg[i4] = make_float4(
                1.0f / (float)max(v.x, 1), 1.0f / (float)max(v.y, 1),
                1.0f / (float)max(v.z, 1), 1.0f / (float)max(v.w, 1));
            *(int4*)&g_cursor[i4] = make_int4(0, 0, 0, 0);
        }
        __syncthreads();
        if (t == 1023) carry_sh = carry + woff + incl;
        __syncthreads();
    }
    if (t == 0) g_off[N_NODES] = carry_sh;
}

__global__ void fill_csr_kernel(const int* __restrict__ src,
                                const int* __restrict__ dst) {
    int e = blockIdx.x * blockDim.x + threadIdx.x;
    if (e < N_EDGES) {
        int d = dst[e];
        int p = atomicAdd(&g_cursor[d], 1);
        g_csr[g_off[d] + p] = src[e];
    }
}

// ---------------- aggregation: one warp per node, pull via CSR ----------------
__global__ void aggregate_kernel(const float* __restrict__ hin) {
    int gw = (blockIdx.x * blockDim.x + threadIdx.x) >> 5;
    int lane = threadIdx.x & 31;
    if (gw >= N_NODES) return;
    int s = g_off[gw], e = g_off[gw + 1];
    const float4* H = (const float4*)hin;
    float4 acc = make_float4(0.f, 0.f, 0.f, 0.f);
    for (int j = s; j < e; j++) {
        int u = __ldg(&g_csr[j]);
        float4 v = __ldg(&H[(size_t)u * 32 + lane]);
        acc.x += v.x; acc.y += v.y; acc.z += v.z; acc.w += v.w;
    }
    float inv = g_invdeg[gw];
    float4 r = make_float4(acc.x * inv, acc.y * inv, acc.z * inv, acc.w * inv);
    ((float4*)g_hn)[(size_t)gw * 32 + lane] = r;
}

// ---------------- weight prep: transpose + bf16 hi/lo split + K-permute ------
__global__ void prep_w_kernel(const float* __restrict__ Ws,
                              const float* __restrict__ Wn) {
    int idx = blockIdx.x * blockDim.x + threadIdx.x;
    if (idx >= 128 * 256) return;
    int n = idx >> 8;
    int k = idx & 255;
    float w = (k < 128) ? Ws[k * 128 + n] : Wn[(k - 128) * 128 + n];
    __nv_bfloat16 hi = __float2bfloat16(w);
    __nv_bfloat16 lo = __float2bfloat16(w - __bfloat162float(hi));
    int group = k >> 4, l = k & 15;
    int p = ((l & 7) >> 1) * 4 + (l & 1) + ((l >> 3) << 1);
    int off = n * KPAD + group * 16 + p;
    g_wthi[off] = hi;
    g_wtlo[off] = lo;
}

// ---------------- persistent bf16-split tensor-core GEMM ---------------------
//   C = Ahi*Whi + Alo*Whi + Ahi*Wlo  (fp32 accum, m16n8k16 bf16 mma.sync)
// W staged once per SM; A double-buffered with register prefetch.
#define W_SMEM (2 * 128 * KPAD)              // bf16 units (hi+lo)
#define ABUF_SMEM (2 * 128 * APAD)           // bf16 units (hi+lo) per buffer
#define GEMM_SMEM_BYTES ((W_SMEM + 2 * ABUF_SMEM) * 2)   // 188416 B

__device__ __forceinline__ void mma_bf16(float c[4], uint32_t a0, uint32_t a1,
                                         uint32_t a2, uint32_t a3,
                                         uint32_t b0, uint32_t b1) {
    asm volatile(
        "mma.sync.aligned.m16n8k16.row.col.f32.bf16.bf16.f32 "
        "{%0,%1,%2,%3}, {%4,%5,%6,%7}, {%8,%9}, {%0,%1,%2,%3};"
        : "+f"(c[0]), "+f"(c[1]), "+f"(c[2]), "+f"(c[3])
        : "r"(a0), "r"(a1), "r"(a2), "r"(a3), "r"(b0), "r"(b1));
}

__global__ void __launch_bounds__(256, 1) sage_gemm_bf16_kernel(
    const float* __restrict__ hin, const float* __restrict__ hn,
    const float* __restrict__ bias, float* __restrict__ out)
{
    extern __shared__ __align__(16) __nv_bfloat16 smem[];
    __nv_bfloat16* sWhi = smem;                       // [128][KPAD]
    __nv_bfloat16* sWlo = sWhi + 128 * KPAD;          // [128][KPAD]
    __nv_bfloat16* sAbuf = sWlo + 128 * KPAD;         // 2 x (hi | lo)

    int tid = threadIdx.x;
    int lane = tid & 31, warp = tid >> 5;
    int warpM = warp & 3, warpN = warp >> 2;          // 4 x 2 warp grid
    int g = lane >> 2, tig = lane & 3;

    // ---- stage weights once per SM ----
    {
        const uint4* s0 = (const uint4*)g_wthi;
        const uint4* s1 = (const uint4*)g_wtlo;
        uint4* d0 = (uint4*)sWhi;
        uint4* d1 = (uint4*)sWlo;
        for (int i = tid; i < (128 * KPAD) / 8; i += 256) {
            d0[i] = s0[i];
            d1[i] = s1[i];
        }
    }

    // ---- bias cached in registers (constant across tiles) ----
    float bx[8], by[8];
    #pragma unroll
    for (int nf = 0; nf < 8; nf++) {
        int col = warpN * 64 + nf * 8 + tig * 2;
        bx[nf] = __ldg(&bias[col]);
        by[nf] = __ldg(&bias[col + 1]);
    }

    // per-thread A-load geometry: idx = tid + 256*i -> row, col4
    const int ptab[4] = {0, 8, 2, 10};

    for (int tile = blockIdx.x; tile < GEMM_TILES; tile += gridDim.x) {
        int m0 = tile * 128;

        float acc[2][8][4];
        #pragma unroll
        for (int mf = 0; mf < 2; mf++)
            #pragma unroll
            for (int nf = 0; nf < 8; nf++)
                #pragma unroll
                for (int r = 0; r < 4; r++) acc[mf][nf][r] = 0.f;

        // preload chunk 0
        float4 pref[4];
        #pragma unroll
        for (int i = 0; i < 4; i++) {
            int idx = tid + 256 * i;
            int r = idx >> 3, c4 = idx & 7;
            int m = m0 + r;
            pref[i] = make_float4(0.f, 0.f, 0.f, 0.f);
            if (m < N_NODES)
                pref[i] = __ldg((const float4*)(hin + (size_t)m * D + c4 * 4));
        }

        for (int kc = 0; kc < 8; kc++) {
            __nv_bfloat16* sAhi = sAbuf + (kc & 1) * ABUF_SMEM;
            __nv_bfloat16* sAlo = sAhi + 128 * APAD;

            // convert prefetched fp32 -> hi/lo bf16, permuted-K smem
            #pragma unroll
            for (int i = 0; i < 4; i++) {
                int idx = tid + 256 * i;
                int r = idx >> 3, c4 = idx & 7;
                float4 v = pref[i];
                __nv_bfloat16 hx = __float2bfloat16(v.x);
                __nv_bfloat16 hy = __float2bfloat16(v.y);
                __nv_bfloat16 hz = __float2bfloat16(v.z);
                __nv_bfloat16 hw = __float2bfloat16(v.w);
                __nv_bfloat16 lx = __float2bfloat16(v.x - __bfloat162float(hx));
                __nv_bfloat16 ly = __float2bfloat16(v.y - __bfloat162float(hy));
                __nv_bfloat16 lz = __float2bfloat16(v.z - __bfloat162float(hz));
                __nv_bfloat16 lw = __float2bfloat16(v.w - __bfloat162float(hw));
                uint32_t hp0 = ((uint32_t)__bfloat16_as_ushort(hy) << 16) |
                               __bfloat16_as_ushort(hx);
                uint32_t hp1 = ((uint32_t)__bfloat16_as_ushort(hw) << 16) |
                               __bfloat16_as_ushort(hz);
                uint32_t lp0 = ((uint32_t)__bfloat16_as_ushort(ly) << 16) |
                               __bfloat16_as_ushort(lx);
                uint32_t lp1 = ((uint32_t)__bfloat16_as_ushort(lw) << 16) |
                               __bfloat16_as_ushort(lz);
                int group = c4 >> 2;
                int p0 = ptab[c4 & 3];
                int base = r * APAD + group * 16;
                uint32_t* AH = (uint32_t*)sAhi;
                uint32_t* AL = (uint32_t*)sAlo;
                AH[(base + p0) >> 1]     = hp0;
                AH[(base + p0 + 4) >> 1] = hp1;
                AL[(base + p0) >> 1]     = lp0;
                AL[(base + p0 + 4) >> 1] = lp1;
            }
            __syncthreads();   // first iteration also covers W staging

            // issue next chunk's loads (consumed next iteration)
            if (kc < 7) {
                int nkc = kc + 1;
                const float* srcp = (nkc < 4) ? hin : hn;
                int koff = (nkc & 3) * 32;
                #pragma unroll
                for (int i = 0; i < 4; i++) {
                    int idx = tid + 256 * i;
                    int r = idx >> 3, c4 = idx & 7;
                    int m = m0 + r;
                    pref[i] = make_float4(0.f, 0.f, 0.f, 0.f);
                    if (m < N_NODES)
                        pref[i] = __ldg((const float4*)(srcp + (size_t)m * D +
                                                        koff + c4 * 4));
                }
            }

            // mma over current buffer
            #pragma unroll
            for (int ks = 0; ks < 2; ks++) {
                int ka = ks * 16;
                int kw = kc * 32 + ks * 16;
                uint32_t Ah[2][4], Al[2][4];
                #pragma unroll
                for (int mf = 0; mf < 2; mf++) {
                    int r0 = warpM * 32 + mf * 16;
                    uint2 t0 = *(const uint2*)&sAhi[(r0 + g) * APAD + ka + tig * 4];
                    uint2 t1 = *(const uint2*)&sAhi[(r0 + g + 8) * APAD + ka + tig * 4];
                    Ah[mf][0] = t0.x; Ah[mf][1] = t1.x; Ah[mf][2] = t0.y; Ah[mf][3] = t1.y;
                    uint2 u0 = *(const uint2*)&sAlo[(r0 + g) * APAD + ka + tig * 4];
                    uint2 u1 = *(const uint2*)&sAlo[(r0 + g + 8) * APAD + ka + tig * 4];
                    Al[mf][0] = u0.x; Al[mf][1] = u1.x; Al[mf][2] = u0.y; Al[mf][3] = u1.y;
                }
                #pragma unroll
                for (int nf = 0; nf < 8; nf++) {
                    int nr = warpN * 64 + nf * 8 + g;
                    uint2 bh = *(const uint2*)&sWhi[nr * KPAD + kw + tig * 4];
                    uint2 bl = *(const uint2*)&sWlo[nr * KPAD + kw + tig * 4];
                    #pragma unroll
                    for (int mf = 0; mf < 2; mf++) {
                        mma_bf16(acc[mf][nf], Ah[mf][0], Ah[mf][1], Ah[mf][2], Ah[mf][3], bh.x, bh.y);
                        mma_bf16(acc[mf][nf], Al[mf][0], Al[mf][1], Al[mf][2], Al[mf][3], bh.x, bh.y);
                        mma_bf16(acc[mf][nf], Ah[mf][0], Ah[mf][1], Ah[mf][2], Ah[mf][3], bl.x, bl.y);
                    }
                }
            }
        }

        // epilogue: + bias, relu, store
        #pragma unroll
        for (int mf = 0; mf < 2; mf++) {
            #pragma unroll
            for (int nf = 0; nf < 8; nf++) {
                int row0 = m0 + warpM * 32 + mf * 16 + g;
                int col = warpN * 64 + nf * 8 + tig * 2;
                if (row0 < N_NODES) {
                    float r0 = acc[mf][nf][0] + bx[nf]; r0 = r0 > 0.f ? r0 : 0.f;
                    float r1 = acc[mf][nf][1] + by[nf]; r1 = r1 > 0.f ? r1 : 0.f;
                    *(float2*)&out[(size_t)row0 * D + col] = make_float2(r0, r1);
                }
                if (row0 + 8 < N_NODES) {
                    float r2 = acc[mf][nf][2] + bx[nf]; r2 = r2 > 0.f ? r2 : 0.f;
                    float r3 = acc[mf][nf][3] + by[nf]; r3 = r3 > 0.f ? r3 : 0.f;
                    *(float2*)&out[(size_t)(row0 + 8) * D + col] = make_float2(r2, r3);
                }
            }
        }
    }
}

// ---------------- launch ----------------
extern "C" void kernel_launch(void* const* d_in, const int* in_sizes, int n_in,
                              void* d_out, int out_size)
{
    const float* x       = (const float*)d_in[0];
    const float* W_self  = (const float*)d_in[1];
    const float* W_neigh = (const float*)d_in[2];
    const float* bias    = (const float*)d_in[3];
    const int*   src     = (const int*)d_in[4];
    const int*   dst     = (const int*)d_in[5];
    float* out = (float*)d_out;

    void *p0, *p1, *pn;
    cudaGetSymbolAddress(&p0, g_h0);
    cudaGetSymbolAddress(&p1, g_h1);
    cudaGetSymbolAddress(&pn, g_hn);
    float* h0 = (float*)p0;
    float* h1 = (float*)p1;
    float* hn = (float*)pn;

    cudaFuncSetAttribute(sage_gemm_bf16_kernel,
                         cudaFuncAttributeMaxDynamicSharedMemorySize,
                         GEMM_SMEM_BYTES);

    zero_deg_kernel<<<(N_NODES + 255) / 256, 256>>>();
    count_deg_kernel<<<(N_EDGES + 255) / 256, 256>>>(dst);
    scan_offsets_kernel<<<1, 1024>>>();
    fill_csr_kernel<<<(N_EDGES + 255) / 256, 256>>>(src, dst);

    const float* hin = x;
    float* houts[3] = {h0, h1, out};
    for (int l = 0; l < L_LAYERS; l++) {
        prep_w_kernel<<<128, 256>>>(W_self + (size_t)l * D * D,
                                    W_neigh + (size_t)l * D * D);
        aggregate_kernel<<<(N_NODES + 7) / 8, 256>>>(hin);
        sage_gemm_bf16_kernel<<<GEMM_GRID, 256, GEMM_SMEM_BYTES>>>(
            hin, hn, bias + (size_t)l * D, houts[l]);
        hin = houts[l];
    }
}